// round 11
// baseline (speedup 1.0000x reference)
#include <cuda_runtime.h>
#include <cuda_fp16.h>
#include <math.h>

#define HDIM 384
#define WDIM 384
#define HW (HDIM*WDIM)            // 147456
#define SUMN 128
#define BATCH 16
#define LAG 8
#define NEGV -1000000000.0f
#define CTILES 72                 // 147456 / (256*8)
#define WTILES 72                 // 147456 / (256*8)

// Scratch (no cudaMalloc allowed)
__device__ __half g_conf[(size_t)SUMN * HW];   // 37.7 MB
__device__ float g_pmc[SUMN * CTILES];         // mean_conf partials
__device__ float g_pov[SUMN * WTILES];         // overlap partials
__device__ float g_pdem[BATCH * CTILES];       // demand partials

__device__ __forceinline__ float blockReduceSum256(float v) {
    __shared__ float ws[8];
    for (int o = 16; o > 0; o >>= 1) v += __shfl_down_sync(0xffffffffu, v, o);
    int lane = threadIdx.x & 31, wid = threadIdx.x >> 5;
    if (lane == 0) ws[wid] = v;
    __syncthreads();
    float r = 0.0f;
    if (wid == 0) {
        r = (lane < 8) ? ws[lane] : 0.0f;
        for (int o = 4; o > 0; o >>= 1) r += __shfl_down_sync(0xffffffffu, r, o);
    }
    __syncthreads();
    return r;  // valid in thread 0
}

// Kernel 1: conf = sigmoid(max(ch0, ch1)) -> fp16; partial sums (no atomics)
__global__ void __launch_bounds__(256) k_conf(const float* __restrict__ psm,
                                              const float* __restrict__ req) {
    int n    = blockIdx.x / CTILES;
    int tile = blockIdx.x % CTILES;
    int p0   = tile * 2048 + threadIdx.x * 8;

    const float* base0 = psm + (size_t)n * 2 * HW + p0;
    const float4 a4l = *(const float4*)(base0);
    const float4 a4h = *(const float4*)(base0 + 4);
    const float4 b4l = *(const float4*)(base0 + HW);
    const float4 b4h = *(const float4*)(base0 + HW + 4);
    float a[8] = {a4l.x, a4l.y, a4l.z, a4l.w, a4h.x, a4h.y, a4h.z, a4h.w};
    float b[8] = {b4l.x, b4l.y, b4l.z, b4l.w, b4h.x, b4h.y, b4h.z, b4h.w};

    __half hs[8];
    float sum = 0.0f;
    #pragma unroll
    for (int u = 0; u < 8; u++) {
        float m = fmaxf(a[u], b[u]);
        float s = __fdividef(1.0f, 1.0f + __expf(-m));
        hs[u] = __float2half_rn(s);
        sum += s;
    }
    *(uint4*)(g_conf + (size_t)n * HW + p0) = *(const uint4*)hs;

    float dsum = 0.0f;
    bool ego = ((n & (LAG - 1)) == 0);
    if (ego) {
        const float* rbase = req + (size_t)n * HW + p0;
        const float4 r4l = *(const float4*)(rbase);
        const float4 r4h = *(const float4*)(rbase + 4);
        dsum = r4l.x + r4l.y + r4l.z + r4l.w + r4h.x + r4h.y + r4h.z + r4h.w;
    }

    float bs = blockReduceSum256(sum);
    if (threadIdx.x == 0) g_pmc[n * CTILES + tile] = bs;
    if (ego) {
        float bd = blockReduceSum256(dsum);
        if (threadIdx.x == 0) g_pdem[(n >> 3) * CTILES + tile] = bd;
    }
}

// Kernel 2 v3: branch-free clamped gathers, 8 px/thread, batched loads.
__global__ void __launch_bounds__(256) k_warp(const float* __restrict__ req,
                                              const float* __restrict__ na) {
    int n    = blockIdx.x / WTILES;
    int tile = blockIdx.x % WTILES;
    int b = n >> 3, l = n & (LAG - 1);

    const float* A = na + (size_t)((b * LAG + 0) * LAG + l) * 6;
    float A00 = __ldg(A + 0), A01 = __ldg(A + 1), A02 = __ldg(A + 2);
    float A10 = __ldg(A + 3), A11 = __ldg(A + 4), A12 = __ldg(A + 5);

    const __half* cimg = g_conf + (size_t)n * HW;
    int p0 = tile * 2048 + threadIdx.x * 8;
    // 8 | 384, so this 8-px run stays within one row.
    int iy = p0 / WDIM;
    int jx = p0 - iy * WDIM;

    const float* rbase = req + (size_t)(b * LAG) * HW + p0;
    const float4 r4l = *(const float4*)(rbase);
    const float4 r4h = *(const float4*)(rbase + 4);
    float di[8] = {r4l.x, r4l.y, r4l.z, r4l.w, r4h.x, r4h.y, r4h.z, r4h.w};

    const float step = 2.0f / 383.0f;
    const float half_ext = 0.5f * (WDIM - 1);   // 191.5
    float gy  = fmaf((float)iy, step, -1.0f);
    float gx0 = fmaf((float)jx, step, -1.0f);
    float px0 = (fmaf(A00, gx0, fmaf(A01, gy, A02)) + 1.0f) * half_ext;
    float py0 = (fmaf(A10, gx0, fmaf(A11, gy, A12)) + 1.0f) * half_ext;
    float dpx = A00 * step * half_ext;
    float dpy = A10 * step * half_ext;

    float sum = 0.0f;
    #pragma unroll
    for (int g = 0; g < 2; g++) {
        int   idx[16];
        float w[16];
        #pragma unroll
        for (int u = 0; u < 4; u++) {
            float uu = (float)(g * 4 + u);
            float px = fmaf(dpx, uu, px0);
            float py = fmaf(dpy, uu, py0);
            float x0f = floorf(px), y0f = floorf(py);
            float wx = px - x0f, wy = py - y0f;
            int x0 = (int)x0f, y0 = (int)y0f;
            // validity folded into weights (no branches)
            float wxv0 = ((unsigned)x0       < (unsigned)WDIM) ? (1.0f - wx) : 0.0f;
            float wxv1 = ((unsigned)(x0 + 1) < (unsigned)WDIM) ? wx          : 0.0f;
            float wyv0 = ((unsigned)y0       < (unsigned)HDIM) ? (1.0f - wy) : 0.0f;
            float wyv1 = ((unsigned)(y0 + 1) < (unsigned)HDIM) ? wy          : 0.0f;
            int xc0 = min(max(x0, 0), WDIM - 1);
            int xc1 = min(max(x0 + 1, 0), WDIM - 1);
            int yc0 = min(max(y0, 0), HDIM - 1);
            int yc1 = min(max(y0 + 1, 0), HDIM - 1);
            idx[u*4+0] = yc0 * WDIM + xc0;  w[u*4+0] = wxv0 * wyv0;
            idx[u*4+1] = yc0 * WDIM + xc1;  w[u*4+1] = wxv1 * wyv0;
            idx[u*4+2] = yc1 * WDIM + xc0;  w[u*4+2] = wxv0 * wyv1;
            idx[u*4+3] = yc1 * WDIM + xc1;  w[u*4+3] = wxv1 * wyv1;
        }
        float v[16];
        #pragma unroll
        for (int e = 0; e < 16; e++) v[e] = __half2float(__ldg(cimg + idx[e]));
        #pragma unroll
        for (int u = 0; u < 4; u++) {
            float val = w[u*4+0]*v[u*4+0] + w[u*4+1]*v[u*4+1]
                      + w[u*4+2]*v[u*4+2] + w[u*4+3]*v[u*4+3];
            sum = fmaf(di[g * 4 + u], val, sum);
        }
    }

    float bs = blockReduceSum256(sum);
    if (threadIdx.x == 0) g_pov[n * WTILES + tile] = bs;
}

// Kernel 3 v5: one block per batch, 512 threads, 1 e-output/thread.
#define NW_QW2 4096
#define NW_KW2 4096
#define NW_EW1 8192
#define NW_EW2 64
#define NW_TOTAL (NW_QW2+NW_KW2+NW_EW1+NW_EW2)   // 16448 floats

__global__ void __launch_bounds__(512)
k_head(const float* __restrict__ na,
       const float* __restrict__ qW1, const float* __restrict__ qb1,
       const float* __restrict__ qW2, const float* __restrict__ qb2,
       const float* __restrict__ kW1, const float* __restrict__ kb1,
       const float* __restrict__ kW2, const float* __restrict__ kb2,
       const float* __restrict__ eW1, const float* __restrict__ eb1,
       const float* __restrict__ eW2, const float* __restrict__ eb2,
       float* __restrict__ out) {
    extern __shared__ float sw[];
    float* w_qW2 = sw;
    float* w_kW2 = w_qW2 + NW_QW2;
    float* w_eW1 = w_kW2 + NW_KW2;
    float* w_eW2 = w_eW1 + NW_EW1;

    __shared__ float s_mc[LAG], s_ov[LAG];
    __shared__ float s_dem;
    __shared__ float s_ego[8];
    __shared__ float s_feat[LAG][8];
    __shared__ float s_hq[64], s_q[64];
    __shared__ float s_hk[LAG][64], s_k[LAG][64];
    __shared__ float s_part[16];

    int b = blockIdx.x;
    int t = threadIdx.x;
    int lane = t & 31, warp = t >> 5;
    const float invHW = 1.0f / (float)HW;

    // Stage 64-wide weight mats (512 threads, float4 = 2048 floats/sweep)
    for (int i = t * 4; i < NW_QW2; i += 2048) *(float4*)(w_qW2 + i) = *(const float4*)(qW2 + i);
    for (int i = t * 4; i < NW_KW2; i += 2048) *(float4*)(w_kW2 + i) = *(const float4*)(kW2 + i);
    for (int i = t * 4; i < NW_EW1; i += 2048) *(float4*)(w_eW1 + i) = *(const float4*)(eW1 + i);
    if (t < 16) *(float4*)(w_eW2 + t * 4) = *(const float4*)(eW2 + t * 4);

    // Reduce partials: warps 0-7 -> mean_conf[l=w] (+warp 0: demand), warps 8-15 -> overlap[l=w-8]
    if (warp < 8) {
        int n = b * LAG + warp;
        float mc = 0.0f, dm = 0.0f;
        for (int i = lane; i < CTILES; i += 32) mc += g_pmc[n * CTILES + i];
        if (warp == 0)
            for (int i = lane; i < CTILES; i += 32) dm += g_pdem[b * CTILES + i];
        for (int o = 16; o > 0; o >>= 1) {
            mc += __shfl_down_sync(0xffffffffu, mc, o);
            dm += __shfl_down_sync(0xffffffffu, dm, o);
        }
        if (lane == 0) {
            s_mc[warp] = mc * invHW;
            if (warp == 0) s_dem = dm * invHW;
        }
    } else {
        int l = warp - 8;
        int n = b * LAG + l;
        float ov = 0.0f;
        for (int i = lane; i < WTILES; i += 32) ov += g_pov[n * WTILES + i];
        for (int o = 16; o > 0; o >>= 1) ov += __shfl_down_sync(0xffffffffu, ov, o);
        if (lane == 0) s_ov[l] = ov * invHW;
    }
    __syncthreads();

    // Features
    if (t < LAG) {
        int l = t;
        const float* A = na + (size_t)((b * LAG + 0) * LAG + l) * 6;
        float dx = A[2], dy = A[5];
        float dist = sqrtf(dx * dx + dy * dy);
        const float* D  = na + (size_t)((b * LAG + l) * LAG + l) * 6;
        const float* D0 = na + (size_t)((b * LAG + 0) * LAG + 0) * 6;
        float yaw  = atan2f(D[3], D[0]);
        float yaw0 = atan2f(D0[3], D0[0]);
        float d = yaw0 - yaw;
        s_feat[l][0] = s_mc[l]; s_feat[l][1] = s_ov[l];
        s_feat[l][2] = dx;      s_feat[l][3] = dy;
        s_feat[l][4] = cosf(d); s_feat[l][5] = sinf(d);
        s_feat[l][6] = dist;    s_feat[l][7] = s_dem;
    } else if (t == LAG) {
        float dm = s_dem, mc0 = s_mc[0];
        s_ego[0] = mc0; s_ego[1] = dm; s_ego[2] = 0.0f; s_ego[3] = 0.0f;
        s_ego[4] = 1.0f; s_ego[5] = 0.0f; s_ego[6] = 0.0f; s_ego[7] = dm;
    }
    __syncthreads();

    int r = t >> 6, j = t & 63;

    // Layer 1: k (1 out/thread, weights direct from global — broadcast across r)
    {
        float acc = kb1[j];
        #pragma unroll
        for (int i = 0; i < 8; i++) acc = fmaf(s_feat[r][i], __ldg(kW1 + i * 64 + j), acc);
        s_hk[r][j] = fmaxf(acc, 0.0f);
        if (t < 64) {
            float aq = qb1[t];
            #pragma unroll
            for (int i = 0; i < 8; i++) aq = fmaf(s_ego[i], __ldg(qW1 + i * 64 + t), aq);
            s_hq[t] = fmaxf(aq, 0.0f);
        }
    }
    __syncthreads();

    // Layer 2
    {
        float acc = kb2[j];
        #pragma unroll
        for (int i = 0; i < 64; i++) acc = fmaf(s_hk[r][i], w_kW2[i * 64 + j], acc);
        s_k[r][j] = acc;
        if (t < 64) {
            float aq = qb2[t];
            #pragma unroll
            for (int i = 0; i < 64; i++) aq = fmaf(s_hq[i], w_qW2[i * 64 + t], aq);
            s_q[t] = aq;
        }
    }
    __syncthreads();

    // e hidden (1 out/thread) + dot with eW2, warp-reduce
    {
        float acc = eb1[j];
        #pragma unroll
        for (int i = 0; i < 64; i++) acc = fmaf(s_q[i],    w_eW1[i * 64 + j], acc);
        #pragma unroll
        for (int i = 0; i < 64; i++) acc = fmaf(s_k[r][i], w_eW1[(64 + i) * 64 + j], acc);
        float contrib = fmaxf(acc, 0.0f) * w_eW2[j];
        for (int o = 16; o > 0; o >>= 1) contrib += __shfl_down_sync(0xffffffffu, contrib, o);
        if (lane == 0) s_part[warp] = contrib;
    }
    __syncthreads();

    if (t < LAG) {
        int l = t;
        float logit = s_part[2 * l] + s_part[2 * l + 1] + eb2[0];
        if (l == 0) logit = NEGV;
        float s = 1.0f / (1.0f + expf(-logit));
        out[b * LAG + l] = fminf(fmaxf(s, 0.0f), 1.0f);
    }
}

extern "C" void kernel_launch(void* const* d_in, const int* in_sizes, int n_in,
                              void* d_out, int out_size) {
    const float* psm  = (const float*)d_in[0];
    const float* req  = (const float*)d_in[1];
    const float* na   = (const float*)d_in[2];
    // d_in[3] = record_len (unused, always L)
    const float* qW1 = (const float*)d_in[4];
    const float* qb1 = (const float*)d_in[5];
    const float* qW2 = (const float*)d_in[6];
    const float* qb2 = (const float*)d_in[7];
    const float* kW1 = (const float*)d_in[8];
    const float* kb1 = (const float*)d_in[9];
    const float* kW2 = (const float*)d_in[10];
    const float* kb2 = (const float*)d_in[11];
    const float* eW1 = (const float*)d_in[12];
    const float* eb1 = (const float*)d_in[13];
    const float* eW2 = (const float*)d_in[14];
    const float* eb2 = (const float*)d_in[15];
    float* out = (float*)d_out;

    cudaFuncSetAttribute(k_head, cudaFuncAttributeMaxDynamicSharedMemorySize,
                         NW_TOTAL * 4);

    k_conf<<<SUMN * CTILES, 256>>>(psm, req);
    k_warp<<<SUMN * WTILES, 256>>>(req, na);
    k_head<<<BATCH, 512, NW_TOTAL * 4>>>(na, qW1, qb1, qW2, qb2, kW1, kb1, kW2, kb2,
                                         eW1, eb1, eW2, eb2, out);
}

// round 13
// speedup vs baseline: 1.6336x; 1.6336x over previous
#include <cuda_runtime.h>
#include <cuda_fp16.h>
#include <math.h>

#define HDIM 384
#define WDIM 384
#define HW (HDIM*WDIM)            // 147456
#define SUMN 128
#define BATCH 16
#define LAG 8
#define NEGV -1000000000.0f
#define CTILES 72                 // 147456 / (256*8)
#define WTILES 144                // 147456 / (256*4)

// Scratch (no cudaMalloc allowed)
__device__ __half g_conf[(size_t)SUMN * HW];   // 37.7 MB
__device__ float g_pmc[SUMN * CTILES];         // mean_conf partials
__device__ float g_pov[SUMN * WTILES];         // overlap partials
__device__ float g_pdem[BATCH * CTILES];       // demand partials

__device__ __forceinline__ float blockReduceSum256(float v) {
    __shared__ float ws[8];
    for (int o = 16; o > 0; o >>= 1) v += __shfl_down_sync(0xffffffffu, v, o);
    int lane = threadIdx.x & 31, wid = threadIdx.x >> 5;
    if (lane == 0) ws[wid] = v;
    __syncthreads();
    float r = 0.0f;
    if (wid == 0) {
        r = (lane < 8) ? ws[lane] : 0.0f;
        for (int o = 4; o > 0; o >>= 1) r += __shfl_down_sync(0xffffffffu, r, o);
    }
    __syncthreads();
    return r;  // valid in thread 0
}

// Kernel 1: conf = sigmoid(max(ch0, ch1)) -> fp16; partial sums (no atomics)
__global__ void __launch_bounds__(256) k_conf(const float* __restrict__ psm,
                                              const float* __restrict__ req) {
    int n    = blockIdx.x / CTILES;
    int tile = blockIdx.x % CTILES;
    int p0   = tile * 2048 + threadIdx.x * 8;

    const float* base0 = psm + (size_t)n * 2 * HW + p0;
    const float4 a4l = *(const float4*)(base0);
    const float4 a4h = *(const float4*)(base0 + 4);
    const float4 b4l = *(const float4*)(base0 + HW);
    const float4 b4h = *(const float4*)(base0 + HW + 4);
    float a[8] = {a4l.x, a4l.y, a4l.z, a4l.w, a4h.x, a4h.y, a4h.z, a4h.w};
    float b[8] = {b4l.x, b4l.y, b4l.z, b4l.w, b4h.x, b4h.y, b4h.z, b4h.w};

    __half hs[8];
    float sum = 0.0f;
    #pragma unroll
    for (int u = 0; u < 8; u++) {
        float m = fmaxf(a[u], b[u]);
        float s = __fdividef(1.0f, 1.0f + __expf(-m));
        hs[u] = __float2half_rn(s);
        sum += s;
    }
    *(uint4*)(g_conf + (size_t)n * HW + p0) = *(const uint4*)hs;

    float dsum = 0.0f;
    bool ego = ((n & (LAG - 1)) == 0);
    if (ego) {
        const float* rbase = req + (size_t)n * HW + p0;
        const float4 r4l = *(const float4*)(rbase);
        const float4 r4h = *(const float4*)(rbase + 4);
        dsum = r4l.x + r4l.y + r4l.z + r4l.w + r4h.x + r4h.y + r4h.z + r4h.w;
    }

    float bs = blockReduceSum256(sum);
    if (threadIdx.x == 0) g_pmc[n * CTILES + tile] = bs;
    if (ego) {
        float bd = blockReduceSum256(dsum);
        if (threadIdx.x == 0) g_pdem[(n >> 3) * CTILES + tile] = bd;
    }
}

// Kernel 2 (R9 form): per-(image,tile), 4 px/thread, branchy gathers.
__global__ void __launch_bounds__(256) k_warp(const float* __restrict__ req,
                                              const float* __restrict__ na) {
    int n    = blockIdx.x / WTILES;
    int tile = blockIdx.x % WTILES;
    int b = n >> 3, l = n & (LAG - 1);

    const float* A = na + (size_t)((b * LAG + 0) * LAG + l) * 6;
    float A00 = __ldg(A + 0), A01 = __ldg(A + 1), A02 = __ldg(A + 2);
    float A10 = __ldg(A + 3), A11 = __ldg(A + 4), A12 = __ldg(A + 5);

    const __half* cimg = g_conf + (size_t)n * HW;
    int p0 = tile * 1024 + threadIdx.x * 4;
    const float4 d4 = *(const float4*)(req + (size_t)(b * LAG) * HW + p0);
    float di[4] = {d4.x, d4.y, d4.z, d4.w};

    const float step = 2.0f / 383.0f;
    float sum = 0.0f;
    #pragma unroll
    for (int u = 0; u < 4; u++) {
        int p = p0 + u;
        int i = p / WDIM;
        int j = p - i * WDIM;
        float gx = fmaf((float)j, step, -1.0f);
        float gy = fmaf((float)i, step, -1.0f);
        float sx = fmaf(A00, gx, fmaf(A01, gy, A02));
        float sy = fmaf(A10, gx, fmaf(A11, gy, A12));
        float px = (sx + 1.0f) * (0.5f * (WDIM - 1));
        float py = (sy + 1.0f) * (0.5f * (HDIM - 1));
        float x0f = floorf(px), y0f = floorf(py);
        float wx = px - x0f, wy = py - y0f;
        int x0 = (int)x0f, y0 = (int)y0f;

        float v00 = 0.0f, v01 = 0.0f, v10 = 0.0f, v11 = 0.0f;
        bool xv0 = (unsigned)x0 < (unsigned)WDIM;
        bool xv1 = (unsigned)(x0 + 1) < (unsigned)WDIM;
        bool yv0 = (unsigned)y0 < (unsigned)HDIM;
        bool yv1 = (unsigned)(y0 + 1) < (unsigned)HDIM;
        if (yv0) {
            const __half* row = cimg + (size_t)y0 * WDIM;
            if (xv0) v00 = __half2float(__ldg(row + x0));
            if (xv1) v01 = __half2float(__ldg(row + x0 + 1));
        }
        if (yv1) {
            const __half* row = cimg + (size_t)(y0 + 1) * WDIM;
            if (xv0) v10 = __half2float(__ldg(row + x0));
            if (xv1) v11 = __half2float(__ldg(row + x0 + 1));
        }
        float top = v00 * (1.0f - wx) + v01 * wx;
        float bot = v10 * (1.0f - wx) + v11 * wx;
        float val = top * (1.0f - wy) + bot * wy;
        sum += di[u] * val;
    }

    float bs = blockReduceSum256(sum);
    if (threadIdx.x == 0) g_pov[n * WTILES + tile] = bs;
}

// Kernel 3 v6: one block per row r, 256 threads, split-i dot products, no staging.
__global__ void __launch_bounds__(256)
k_head(const float* __restrict__ na,
       const float* __restrict__ qW1, const float* __restrict__ qb1,
       const float* __restrict__ qW2, const float* __restrict__ qb2,
       const float* __restrict__ kW1, const float* __restrict__ kb1,
       const float* __restrict__ kW2, const float* __restrict__ kb2,
       const float* __restrict__ eW1, const float* __restrict__ eb1,
       const float* __restrict__ eW2, const float* __restrict__ eb2,
       float* __restrict__ out) {
    __shared__ float s_mc, s_ov, s_dem, s_mc0;
    __shared__ float s_ego[8], s_feat[8];
    __shared__ float s_hq[64], s_hk[64];
    __shared__ float s_p2[2][128];       // layer-2 partials (2 i-halves x 128 outs)
    __shared__ float s_q[64], s_k[64];
    __shared__ float s_pe[4][64];        // e-layer partials (4 i-quarters x 64 outs)
    __shared__ float s_ws[2];

    int r = blockIdx.x;
    int b = r >> 3, l = r & (LAG - 1);
    int t = threadIdx.x;
    int lane = t & 31, warp = t >> 5;
    const float invHW = 1.0f / (float)HW;

    // Phase A: reduce this row's partials (4 warps, one quantity each)
    if (warp == 0) {
        float v = 0.0f;
        for (int i = lane; i < CTILES; i += 32) v += g_pmc[r * CTILES + i];
        for (int o = 16; o > 0; o >>= 1) v += __shfl_down_sync(0xffffffffu, v, o);
        if (lane == 0) s_mc = v * invHW;
    } else if (warp == 1) {
        float v = 0.0f;
        for (int i = lane; i < WTILES; i += 32) v += g_pov[r * WTILES + i];
        for (int o = 16; o > 0; o >>= 1) v += __shfl_down_sync(0xffffffffu, v, o);
        if (lane == 0) s_ov = v * invHW;
    } else if (warp == 2) {
        float v = 0.0f;
        for (int i = lane; i < CTILES; i += 32) v += g_pdem[b * CTILES + i];
        for (int o = 16; o > 0; o >>= 1) v += __shfl_down_sync(0xffffffffu, v, o);
        if (lane == 0) s_dem = v * invHW;
    } else {
        float v = 0.0f;
        int n0 = b * LAG;
        for (int i = lane; i < CTILES; i += 32) v += g_pmc[n0 * CTILES + i];
        for (int o = 16; o > 0; o >>= 1) v += __shfl_down_sync(0xffffffffu, v, o);
        if (lane == 0) s_mc0 = v * invHW;
    }
    __syncthreads();

    // Phase B: features (thread 0)
    if (t == 0) {
        float dm = s_dem;
        const float* A = na + (size_t)((b * LAG + 0) * LAG + l) * 6;
        float dx = A[2], dy = A[5];
        float dist = sqrtf(dx * dx + dy * dy);
        const float* D  = na + (size_t)((b * LAG + l) * LAG + l) * 6;
        const float* D0 = na + (size_t)((b * LAG + 0) * LAG + 0) * 6;
        float yaw  = atan2f(D[3], D[0]);
        float yaw0 = atan2f(D0[3], D0[0]);
        float d = yaw0 - yaw;
        s_feat[0] = s_mc;    s_feat[1] = s_ov;
        s_feat[2] = dx;      s_feat[3] = dy;
        s_feat[4] = cosf(d); s_feat[5] = sinf(d);
        s_feat[6] = dist;    s_feat[7] = dm;
        s_ego[0] = s_mc0; s_ego[1] = dm; s_ego[2] = 0.0f; s_ego[3] = 0.0f;
        s_ego[4] = 1.0f;  s_ego[5] = 0.0f; s_ego[6] = 0.0f; s_ego[7] = dm;
    }
    __syncthreads();

    // Layer 1 (8-wide): t<128 -> path = t>>6 (0=q,1=k), j = t&63
    if (t < 128) {
        int path = t >> 6, j = t & 63;
        const float* w = path ? kW1 : qW1;
        const float* x = path ? s_feat : s_ego;
        float acc = path ? kb1[j] : qb1[j];
        #pragma unroll
        for (int i = 0; i < 8; i++) acc = fmaf(x[i], __ldg(w + i * 64 + j), acc);
        (path ? s_hk : s_hq)[j] = fmaxf(acc, 0.0f);
    }
    __syncthreads();

    // Layer 2 (64-wide): out = t&127 (path,j), ihalf = t>>7; 32 loads/thread
    {
        int o = t & 127, ihalf = t >> 7;
        int path = o >> 6, j = o & 63;
        const float* w = path ? kW2 : qW2;
        const float* x = path ? s_hk : s_hq;
        float acc = 0.0f;
        int i0 = ihalf * 32;
        #pragma unroll
        for (int i = 0; i < 32; i++) acc = fmaf(x[i0 + i], __ldg(w + (i0 + i) * 64 + j), acc);
        s_p2[ihalf][o] = acc;
    }
    __syncthreads();
    if (t < 128) {
        int path = t >> 6, j = t & 63;
        float acc = s_p2[0][t] + s_p2[1][t] + (path ? kb2[j] : qb2[j]);
        (path ? s_k : s_q)[j] = acc;
    }
    __syncthreads();

    // e-layer (128-wide input [q,k]): j = t&63, quarter = t>>6; 32 loads/thread
    {
        int j = t & 63, quarter = t >> 6;
        const float* x = (quarter < 2) ? s_q : s_k;
        int xi0 = (quarter & 1) * 32;
        int wi0 = quarter * 32;                 // row in eW1 (input index)
        float acc = 0.0f;
        #pragma unroll
        for (int i = 0; i < 32; i++)
            acc = fmaf(x[xi0 + i], __ldg(eW1 + (wi0 + i) * 64 + j), acc);
        s_pe[quarter][j] = acc;
    }
    __syncthreads();

    // Final: relu + dot eW2 (t<64), 2-warp reduce
    if (t < 64) {
        int j = t;
        float h = s_pe[0][j] + s_pe[1][j] + s_pe[2][j] + s_pe[3][j] + eb1[j];
        float eh = fmaxf(h, 0.0f) * __ldg(eW2 + j);
        for (int o = 16; o > 0; o >>= 1) eh += __shfl_down_sync(0xffffffffu, eh, o);
        if ((t & 31) == 0) s_ws[t >> 5] = eh;
    }
    __syncthreads();
    if (t == 0) {
        float logit = s_ws[0] + s_ws[1] + eb2[0];
        if (l == 0) logit = NEGV;
        float s = 1.0f / (1.0f + expf(-logit));
        out[r] = fminf(fmaxf(s, 0.0f), 1.0f);
    }
}

extern "C" void kernel_launch(void* const* d_in, const int* in_sizes, int n_in,
                              void* d_out, int out_size) {
    const float* psm  = (const float*)d_in[0];
    const float* req  = (const float*)d_in[1];
    const float* na   = (const float*)d_in[2];
    // d_in[3] = record_len (unused, always L)
    const float* qW1 = (const float*)d_in[4];
    const float* qb1 = (const float*)d_in[5];
    const float* qW2 = (const float*)d_in[6];
    const float* qb2 = (const float*)d_in[7];
    const float* kW1 = (const float*)d_in[8];
    const float* kb1 = (const float*)d_in[9];
    const float* kW2 = (const float*)d_in[10];
    const float* kb2 = (const float*)d_in[11];
    const float* eW1 = (const float*)d_in[12];
    const float* eb1 = (const float*)d_in[13];
    const float* eW2 = (const float*)d_in[14];
    const float* eb2 = (const float*)d_in[15];
    float* out = (float*)d_out;

    k_conf<<<SUMN * CTILES, 256>>>(psm, req);
    k_warp<<<SUMN * WTILES, 256>>>(req, na);
    k_head<<<SUMN, 256>>>(na, qW1, qb1, qW2, qb2, kW1, kb1, kW2, kb2,
                          eW1, eb1, eW2, eb2, out);
}